// round 11
// baseline (speedup 1.0000x reference)
#include <cuda_runtime.h>
#include <cuda_bf16.h>
#include <math_constants.h>

// Problem constants
#define BB   512
#define T1   127
#define EE   256
#define HH   256
#define G4   1024
#define NL   3
#define BH   (BB*HH)

// ---------------- device scratch ----------------
__device__ __nv_bfloat16 g_encproj_bf[(size_t)BB * T1 * EE];  // 33.3 MB
__device__ float g_qproj [BB * EE];                // split-K partial 0
__device__ float g_qproj2[BB * EE];                // split-K partial 1
__device__ float g_gates [(size_t)NL * BB * G4];   // Whh partial (K 0:128) + biases
__device__ float g_gates2[(size_t)NL * BB * G4];   // Whh partial (K 128:256)
__device__ float g_h[NL * BH];
__device__ float g_c[NL * BH];
__device__ float g_context[BB * EE];

// ---------------- fast math helpers ----------------
__device__ __forceinline__ float tanha(float x) {
    float r; asm("tanh.approx.f32 %0, %1;" : "=f"(r) : "f"(x)); return r;
}
__device__ __forceinline__ float ex2f(float x) {
    float r; asm("ex2.approx.f32 %0, %1;" : "=f"(r) : "f"(x)); return r;
}
__device__ __forceinline__ float rcpf(float x) {
    float r; asm("rcp.approx.f32 %0, %1;" : "=f"(r) : "f"(x)); return r;
}
__device__ __forceinline__ float sigf(float x) {
    return rcpf(1.0f + ex2f(-1.4426950408889634f * x));
}
__device__ __forceinline__ float tanh_ex(float x) {
    float z = ex2f(2.8853900817779268f * x);
    return fmaf(-2.0f, rcpf(z + 1.0f), 1.0f);
}
__device__ __forceinline__ float2 ffma2(float2 a, float2 b, float2 c) {
    union U { float2 f; unsigned long long u; };
    U ua, ub, uc, ud;
    ua.f = a; ub.f = b; uc.f = c;
    asm("fma.rn.f32x2 %0, %1, %2, %3;" : "=l"(ud.u) : "l"(ua.u), "l"(ub.u), "l"(uc.u));
    return ud.f;
}
// streaming loads (evict-first): single-use sweeps must not evict weights from L2
__device__ __forceinline__ float ldcs_f(const float* p) {
    float v; asm volatile("ld.global.cs.f32 %0, [%1];" : "=f"(v) : "l"(p)); return v;
}
__device__ __forceinline__ unsigned ldcs_u32(const unsigned* p) {
    unsigned v; asm volatile("ld.global.cs.u32 %0, [%1];" : "=r"(v) : "l"(p)); return v;
}

// ---------------- 64x64 tile GEMM core (micro 4x4, f32x2) ----------------
__device__ __forceinline__ void mm64_inner(const float (*As)[68], const float (*Ws)[68],
                                           float2 acc[4][2], int tx, int ty)
{
#pragma unroll
    for (int kk = 0; kk < 32; kk++) {
        float4 a = *(const float4*)&As[kk][ty * 4];
        float4 w = *(const float4*)&Ws[kk][tx * 4];
        float2 wlo = make_float2(w.x, w.y), whi = make_float2(w.z, w.w);
        acc[0][0] = ffma2(make_float2(a.x, a.x), wlo, acc[0][0]);
        acc[0][1] = ffma2(make_float2(a.x, a.x), whi, acc[0][1]);
        acc[1][0] = ffma2(make_float2(a.y, a.y), wlo, acc[1][0]);
        acc[1][1] = ffma2(make_float2(a.y, a.y), whi, acc[1][1]);
        acc[2][0] = ffma2(make_float2(a.z, a.z), wlo, acc[2][0]);
        acc[2][1] = ffma2(make_float2(a.z, a.z), whi, acc[2][1]);
        acc[3][0] = ffma2(make_float2(a.w, a.w), wlo, acc[3][0]);
        acc[3][1] = ffma2(make_float2(a.w, a.w), whi, acc[3][1]);
    }
}

#define TILE_WR(dst, v0, v1, kq, r) \
    dst[(kq)+0][r]=v0.x; dst[(kq)+1][r]=v0.y; dst[(kq)+2][r]=v0.z; dst[(kq)+3][r]=v0.w; \
    dst[(kq)+4][r]=v1.x; dst[(kq)+5][r]=v1.y; dst[(kq)+6][r]=v1.z; dst[(kq)+7][r]=v1.w;

// ---------------- Whh-gates tile, split-K half (kh in {0,1}) ----------------
__device__ void gates_tile_kh(int l, int r, int kh, const float* __restrict__ whh,
                              const float* __restrict__ bih, const float* __restrict__ bhh,
                              float (*As)[68], float (*Ws)[68], int tid)
{
    const int tx = tid & 15, ty = tid >> 4;
    const int rl = tid & 63, kq = (tid >> 6) * 8;
    const int b0 = (r & 7) * 64, gu0 = (r >> 3) * 64;
    const int ko = kh * 128;
    const float* S = g_h + l * BH;
    const float* W = whh + (size_t)l * G4 * HH;

    float2 acc[4][2];
#pragma unroll
    for (int i = 0; i < 4; i++) { acc[i][0] = make_float2(0.f, 0.f); acc[i][1] = make_float2(0.f, 0.f); }

    for (int kc = 0; kc < 128; kc += 32) {
        const float* sp = &S[(size_t)(b0 + rl) * 256 + ko + kc + kq];
        float4 v0 = *(const float4*)sp, v1 = *(const float4*)(sp + 4);
        const float* wp = &W[(size_t)(gu0 + rl) * 256 + ko + kc + kq];
        float4 u0 = *(const float4*)wp, u1 = *(const float4*)(wp + 4);
        TILE_WR(As, v0, v1, kq, rl);
        TILE_WR(Ws, u0, u1, kq, rl);
        __syncthreads();
        mm64_inner(As, Ws, acc, tx, ty);
        __syncthreads();
    }
    const int gu = gu0 + tx * 4;
    if (kh == 0) {
        float4 bb1 = *(const float4*)&bih[l * G4 + gu];
        float4 bb2 = *(const float4*)&bhh[l * G4 + gu];
#pragma unroll
        for (int i = 0; i < 4; i++) {
            float4 o = make_float4(acc[i][0].x + bb1.x + bb2.x,
                                   acc[i][0].y + bb1.y + bb2.y,
                                   acc[i][1].x + bb1.z + bb2.z,
                                   acc[i][1].y + bb1.w + bb2.w);
            *(float4*)&g_gates[((size_t)l * BB + b0 + ty * 4 + i) * G4 + gu] = o;
        }
    } else {
#pragma unroll
        for (int i = 0; i < 4; i++) {
            float4 o = make_float4(acc[i][0].x, acc[i][0].y, acc[i][1].x, acc[i][1].y);
            *(float4*)&g_gates2[((size_t)l * BB + b0 + ty * 4 + i) * G4 + gu] = o;
        }
    }
}

// ---------------- qproj tile, split-K half (kh=0: h0 pass, kh=1: c0 pass) ----------------
__device__ void qproj_tile_kh(int qb, int kh, const float* __restrict__ w1,
                              float (*As)[68], float (*Ws)[68], int tid)
{
    const int tx = tid & 15, ty = tid >> 4;
    const int rl = tid & 63, kq = (tid >> 6) * 8;
    const int b0 = (qb & 7) * 64, f0 = (qb >> 3) * 64;
    const float* S = kh ? g_c : g_h;   // layer 0 slices at offset 0

    float2 acc[4][2];
#pragma unroll
    for (int i = 0; i < 4; i++) { acc[i][0] = make_float2(0.f, 0.f); acc[i][1] = make_float2(0.f, 0.f); }

    for (int kc = 0; kc < 256; kc += 32) {
        const float* sp = &S[(size_t)(b0 + rl) * 256 + kc + kq];
        float4 v0 = *(const float4*)sp, v1 = *(const float4*)(sp + 4);
        const float* wp = &w1[(size_t)(f0 + rl) * 768 + kh * 256 + kc + kq];
        float4 u0 = *(const float4*)wp, u1 = *(const float4*)(wp + 4);
        TILE_WR(As, v0, v1, kq, rl);
        TILE_WR(Ws, u0, u1, kq, rl);
        __syncthreads();
        mm64_inner(As, Ws, acc, tx, ty);
        __syncthreads();
    }
    float* dst = kh ? g_qproj2 : g_qproj;
#pragma unroll
    for (int i = 0; i < 4; i++) {
        float4 o = make_float4(acc[i][0].x, acc[i][0].y, acc[i][1].x, acc[i][1].y);
        *(float4*)&dst[(b0 + ty * 4 + i) * 256 + f0 + tx * 4] = o;
    }
}

// ---------------- LSTM layer tile (R3-proven body; reads both gate partials) ----------------
__device__ void lstm_tile(int l, int fbid, const float* __restrict__ wihr,
                          float (*xs)[34], float (*ws)[32][34])
{
    const int b0 = (fbid & 15) * 32;
    const int u0 = (fbid >> 4) * 32;
    const int tid = threadIdx.x;
    const int tx = tid & 15, ty = tid >> 4;
    const int ul = tx * 2, bl = ty * 2;

    const float* hin = g_h + (l - 1) * BH;
    const float* Wih = wihr + (size_t)(l - 1) * G4 * HH;

    float2 acc[2][4];
#pragma unroll
    for (int i = 0; i < 2; i++)
#pragma unroll
        for (int g = 0; g < 4; g++) acc[i][g] = make_float2(0.f, 0.f);

    const int ldb = tid >> 3, ldk = (tid & 7) * 4;
    for (int kc = 0; kc < 256; kc += 32) {
        {
            float4 v = *(const float4*)&hin[(size_t)(b0 + ldb) * 256 + kc + ldk];
            xs[ldk + 0][ldb] = v.x; xs[ldk + 1][ldb] = v.y;
            xs[ldk + 2][ldb] = v.z; xs[ldk + 3][ldb] = v.w;
        }
#pragma unroll
        for (int i = tid; i < 1024; i += 256) {
            int g = i >> 8, u = (i >> 3) & 31, kqw = (i & 7) * 4;
            float4 v = *(const float4*)&Wih[(size_t)((g << 8) + u0 + u) * 256 + kc + kqw];
            ws[g][kqw + 0][u] = v.x; ws[g][kqw + 1][u] = v.y;
            ws[g][kqw + 2][u] = v.z; ws[g][kqw + 3][u] = v.w;
        }
        __syncthreads();
#pragma unroll
        for (int kk = 0; kk < 32; kk++) {
            float2 a = *(const float2*)&xs[kk][bl];
            float2 ax = make_float2(a.x, a.x);
            float2 ay = make_float2(a.y, a.y);
#pragma unroll
            for (int g = 0; g < 4; g++) {
                float2 w = *(const float2*)&ws[g][kk][ul];
                acc[0][g] = ffma2(ax, w, acc[0][g]);
                acc[1][g] = ffma2(ay, w, acc[1][g]);
            }
        }
        __syncthreads();
    }

#pragma unroll
    for (int i = 0; i < 2; i++) {
#pragma unroll
        for (int j = 0; j < 2; j++) {
            int b = b0 + bl + i;
            int u = u0 + ul + j;
            const float* gb  = &g_gates [((size_t)l * BB + b) * G4];
            const float* gb2 = &g_gates2[((size_t)l * BB + b) * G4];
            float gi = (j ? acc[i][0].y : acc[i][0].x) + gb[0 * 256 + u] + gb2[0 * 256 + u];
            float gf = (j ? acc[i][1].y : acc[i][1].x) + gb[1 * 256 + u] + gb2[1 * 256 + u];
            float gg = (j ? acc[i][2].y : acc[i][2].x) + gb[2 * 256 + u] + gb2[2 * 256 + u];
            float go = (j ? acc[i][3].y : acc[i][3].x) + gb[3 * 256 + u] + gb2[3 * 256 + u];
            float co = g_c[l * BH + b * 256 + u];
            float cn = sigf(gf) * co + sigf(gi) * tanh_ex(gg);
            float hn = sigf(go) * tanh_ex(cn);
            g_c[l * BH + b * 256 + u] = cn;
            g_h[l * BH + b * 256 + u] = hn;
        }
    }
}

// ---------------- init: h=c=0, qproj partials=0, gates0/1 = biases / 0 ----------------
__global__ __launch_bounds__(256) void init_kernel(
    const float* __restrict__ bih, const float* __restrict__ bhh)
{
    int i = blockIdx.x * blockDim.x + threadIdx.x;
    if (i < NL * BH) { g_h[i] = 0.0f; g_c[i] = 0.0f; }
    if (i < BB * EE) { g_qproj[i] = 0.0f; g_qproj2[i] = 0.0f; }
    if (i < BB * G4) {
        int gu = i & 1023;
        g_gates [i] = bih[gu] + bhh[gu];                             // layer 0, kh=0 (+biases)
        g_gates2[i] = 0.0f;                                          // layer 0, kh=1
        g_gates [(size_t)BB * G4 + i] = bih[G4 + gu] + bhh[G4 + gu]; // layer 1
        g_gates2[(size_t)BB * G4 + i] = 0.0f;
    }
}

// ---------------- enc_proj GEMM (once), bf16 output ----------------
__global__ __launch_bounds__(256) void encproj_kernel(
    const float* __restrict__ x, const float* __restrict__ w1,
    const float* __restrict__ b1)
{
    __shared__ float As[32][68];
    __shared__ float Ws[32][68];
    const int m0 = blockIdx.x * 64;
    const int f0 = blockIdx.y * 64;
    const int tid = threadIdx.x;
    const int tx = tid & 15, ty = tid >> 4;
    const int rl = tid & 63, kq = (tid >> 6) * 8;

    float2 acc[4][2];
#pragma unroll
    for (int i = 0; i < 4; i++) { acc[i][0] = make_float2(0.f, 0.f); acc[i][1] = make_float2(0.f, 0.f); }

    for (int kc = 0; kc < 256; kc += 32) {
        const float* sp = &x[(size_t)(m0 + rl) * 256 + kc + kq];
        float4 v0 = *(const float4*)sp, v1 = *(const float4*)(sp + 4);
        const float* wp = &w1[(size_t)(f0 + rl) * 768 + 512 + kc + kq];
        float4 u0 = *(const float4*)wp, u1 = *(const float4*)(wp + 4);
        TILE_WR(As, v0, v1, kq, rl);
        TILE_WR(Ws, u0, u1, kq, rl);
        __syncthreads();
        mm64_inner(As, Ws, acc, tx, ty);
        __syncthreads();
    }

    float4 bias = *(const float4*)&b1[f0 + tx * 4];
#pragma unroll
    for (int i = 0; i < 4; i++) {
        __nv_bfloat162 p0, p1;
        p0.x = __float2bfloat16_rn(acc[i][0].x + bias.x);
        p0.y = __float2bfloat16_rn(acc[i][0].y + bias.y);
        p1.x = __float2bfloat16_rn(acc[i][1].x + bias.z);
        p1.y = __float2bfloat16_rn(acc[i][1].y + bias.w);
        __nv_bfloat162* dst = (__nv_bfloat162*)&g_encproj_bf[(size_t)(m0 + ty * 4 + i) * 256 + f0 + tx * 4];
        dst[0] = p0; dst[1] = p1;
    }
}

// ---------------- K1: gates2 dual-tile (split-K) + fused attention ----------------
__global__ __launch_bounds__(512) void k1_kernel(
    const float* __restrict__ x,    const float* __restrict__ yh,
    const float* __restrict__ w2,   const float* __restrict__ fcw,
    const float* __restrict__ fcb,  const float* __restrict__ wih0,
    const float* __restrict__ whh,  const float* __restrict__ bih,
    const float* __restrict__ bhh,  int s)
{
    __shared__ float s_g[2][64][68];            // two gate tile halves
    __shared__ float s_qp[256], s_w2[256], s_sc[128];
    __shared__ float s_m[4], s_s[4];
    __shared__ float s_ctx[2][256];
    __shared__ float s_y[8];
    __shared__ float s_inv, s_yt;

    const int bid = blockIdx.x;
    const int tid = threadIdx.x;

    if (bid < 128) {                             // gates layer 2: 256 split-K tiles, dual
        const int half = tid >> 8, st = tid & 255;
        const int t = bid * 2 + half;            // tile id: r = t>>1, kh = t&1
        gates_tile_kh(2, t >> 1, t & 1, whh, bih, bhh,
                      (float(*)[68])&s_g[half][0], (float(*)[68])&s_g[half][32], st);
        return;
    }
    const int b = bid - 128;
    const int warp = tid >> 5, lane = tid & 31;

    if (tid < 256) {
        s_qp[tid] = g_qproj[b * 256 + tid] + g_qproj2[b * 256 + tid];
        s_w2[tid] = w2[tid];
    }
    __syncthreads();

    // scores -> s_sc; enc_proj is single-use -> streaming load
    for (int t = warp; t < T1; t += 16) {
        const unsigned* er =
            (const unsigned*)(g_encproj_bf + ((size_t)b * T1 + t) * 256);
        float ps = 0.0f;
#pragma unroll
        for (int i = 0; i < 4; i++) {
            int e2 = lane + i * 32;
            unsigned raw = ldcs_u32(er + e2);
            __nv_bfloat162 evb = *(__nv_bfloat162*)&raw;
            float2 ev = __bfloat1622float2(evb);
            int e = e2 * 2;
            ps += s_w2[e]     * tanha(s_qp[e]     + ev.x);
            ps += s_w2[e + 1] * tanha(s_qp[e + 1] + ev.y);
        }
#pragma unroll
        for (int o = 16; o; o >>= 1) ps += __shfl_xor_sync(0xffffffffu, ps, o);
        if (lane == 0) s_sc[t] = ps;
    }
    __syncthreads();

    if (tid < 128) {
        float v = (tid < T1) ? s_sc[tid] : -CUDART_INF_F;
        float m = v;
#pragma unroll
        for (int o = 16; o; o >>= 1) m = fmaxf(m, __shfl_xor_sync(0xffffffffu, m, o));
        if (lane == 0) s_m[warp] = m;
    }
    __syncthreads();
    if (tid < 128) {
        float mx = fmaxf(fmaxf(s_m[0], s_m[1]), fmaxf(s_m[2], s_m[3]));
        float v = (tid < T1) ? s_sc[tid] : -CUDART_INF_F;
        float e_ = (tid < T1) ? ex2f((v - mx) * 1.4426950408889634f) : 0.0f;
        float ss = e_;
#pragma unroll
        for (int o = 16; o; o >>= 1) ss += __shfl_xor_sync(0xffffffffu, ss, o);
        if (lane == 0) s_s[warp] = ss;
        s_sc[tid] = e_;
    }
    __syncthreads();
    if (tid == 0) s_inv = 1.0f / (s_s[0] + s_s[1] + s_s[2] + s_s[3]);
    __syncthreads();

    // context: x is single-use per step -> streaming loads
    {
        const int e = tid & 255, half = tid >> 8;
        const int t0 = half * 64;
        const int t1 = (half == 0) ? 64 : T1;
        const float* xb = x + (size_t)b * T1 * 256 + e;
        float a0 = 0.f, a1 = 0.f, a2 = 0.f, a3 = 0.f;
        int t = t0;
#pragma unroll 2
        for (; t + 4 <= t1; t += 4) {
            a0 = fmaf(s_sc[t + 0], ldcs_f(&xb[(size_t)(t + 0) * 256]), a0);
            a1 = fmaf(s_sc[t + 1], ldcs_f(&xb[(size_t)(t + 1) * 256]), a1);
            a2 = fmaf(s_sc[t + 2], ldcs_f(&xb[(size_t)(t + 2) * 256]), a2);
            a3 = fmaf(s_sc[t + 3], ldcs_f(&xb[(size_t)(t + 3) * 256]), a3);
        }
        for (; t < t1; t++) a0 = fmaf(s_sc[t], ldcs_f(&xb[(size_t)t * 256]), a0);
        s_ctx[half][e] = (a0 + a1) + (a2 + a3);
    }
    __syncthreads();

    float ctx = 0.0f;
    if (tid < 256) {
        ctx = (s_ctx[0][tid] + s_ctx[1][tid]) * s_inv;
        g_context[b * 256 + tid] = ctx;
        float yv = ctx * fcw[tid];
#pragma unroll
        for (int o = 16; o; o >>= 1) yv += __shfl_xor_sync(0xffffffffu, yv, o);
        if (lane == 0) s_y[warp] = yv;
    }
    __syncthreads();
    if (tid == 0) {
        float tot = 0.0f;
#pragma unroll
        for (int w = 0; w < 8; w++) tot += s_y[w];
        s_yt = tot + yh[b * T1 + s] * fcw[256] + fcb[0];
    }
    __syncthreads();

    if (tid < 256) {
        const float yt = s_yt;
        const int u = tid;
        const float* gb  = &g_gates [(size_t)b * G4];
        const float* gb2 = &g_gates2[(size_t)b * G4];
        float gi = fmaf(yt, wih0[0 * 256 + u], gb[0 * 256 + u] + gb2[0 * 256 + u]);
        float gf = fmaf(yt, wih0[1 * 256 + u], gb[1 * 256 + u] + gb2[1 * 256 + u]);
        float gg = fmaf(yt, wih0[2 * 256 + u], gb[2 * 256 + u] + gb2[2 * 256 + u]);
        float go = fmaf(yt, wih0[3 * 256 + u], gb[3 * 256 + u] + gb2[3 * 256 + u]);
        float co = g_c[b * 256 + u];
        float cn = sigf(gf) * co + sigf(gi) * tanh_ex(gg);
        float hn = sigf(go) * tanh_ex(cn);
        g_c[b * 256 + u] = cn;
        g_h[b * 256 + u] = hn;
    }
}

// ---------------- K2: lstm1(s) | qproj(s+1) split-K | gates0(s+1) split-K ----------------
__global__ __launch_bounds__(256) void k2_kernel(
    const float* __restrict__ wihr, const float* __restrict__ w1,
    const float* __restrict__ whh,  const float* __restrict__ bih,
    const float* __restrict__ bhh)
{
    __shared__ float As[32][68];
    __shared__ float Ws[32][68];
    __shared__ float xs[32][34];
    __shared__ float ws[4][32][34];

    const int bid = blockIdx.x;
    if (bid < 128) {
        lstm_tile(1, bid, wihr, xs, ws);                      // LSTM layer 1 THIS step
    } else if (bid < 192) {
        const int t = bid - 128;                              // qproj: 64 half-tiles
        qproj_tile_kh(t >> 1, t & 1, w1, As, Ws, threadIdx.x);
    } else {
        const int t = bid - 192;                              // gates0: 256 half-tiles
        gates_tile_kh(0, t >> 1, t & 1, whh, bih, bhh, As, Ws, threadIdx.x);
    }
}

// ---------------- K3: lstm2(s) | gates1(s+1) split-K ----------------
__global__ __launch_bounds__(256) void k3_kernel(
    const float* __restrict__ wihr, const float* __restrict__ whh,
    const float* __restrict__ bih,  const float* __restrict__ bhh)
{
    __shared__ float As[32][68];
    __shared__ float Ws[32][68];
    __shared__ float xs[32][34];
    __shared__ float ws[4][32][34];

    const int bid = blockIdx.x;
    if (bid < 128) {
        lstm_tile(2, bid, wihr, xs, ws);                      // LSTM layer 2 THIS step
    } else {
        const int t = bid - 128;                              // gates1: 256 half-tiles
        gates_tile_kh(1, t >> 1, t & 1, whh, bih, bhh, As, Ws, threadIdx.x);
    }
}

// ---------------- final projection ----------------
__global__ __launch_bounds__(256) void final_kernel(
    const float* __restrict__ fcfw, const float* __restrict__ fcfb,
    float* __restrict__ out)
{
    const int b = blockIdx.x;
    const int tid = threadIdx.x;
    const int warp = tid >> 5, lane = tid & 31;
    __shared__ float s_r[8];

    float v = g_h[b * 256 + tid] * fcfw[tid]
            + g_context[b * 256 + tid] * fcfw[256 + tid];
#pragma unroll
    for (int o = 16; o; o >>= 1) v += __shfl_xor_sync(0xffffffffu, v, o);
    if (lane == 0) s_r[warp] = v;
    __syncthreads();
    if (tid == 0) {
        float tot = 0.0f;
#pragma unroll
        for (int w = 0; w < 8; w++) tot += s_r[w];
        out[b] = tot + fcfb[0];
    }
}

// ---------------- host launcher ----------------
extern "C" void kernel_launch(void* const* d_in, const int* in_sizes, int n_in,
                              void* d_out, int out_size)
{
    const float* x    = (const float*)d_in[0];
    const float* yh   = (const float*)d_in[1];
    const float* w1   = (const float*)d_in[2];
    const float* b1   = (const float*)d_in[3];
    const float* w2   = (const float*)d_in[4];
    const float* wih0 = (const float*)d_in[6];
    const float* wihr = (const float*)d_in[7];
    const float* whh  = (const float*)d_in[8];
    const float* bih  = (const float*)d_in[9];
    const float* bhh  = (const float*)d_in[10];
    const float* fcw  = (const float*)d_in[11];
    const float* fcb  = (const float*)d_in[12];
    const float* fcfw = (const float*)d_in[13];
    const float* fcfb = (const float*)d_in[14];
    float* out = (float*)d_out;

    init_kernel<<<2048, 256>>>(bih, bhh);
    encproj_kernel<<<dim3(1016, 4), 256>>>(x, w1, b1);

    for (int s = 0; s < T1; s++) {
        k1_kernel<<<640, 512>>>(x, yh, w2, fcw, fcb, wih0, whh, bih, bhh, s);
        if (s < T1 - 1) {
            k2_kernel<<<448, 256>>>(wihr, w1, whh, bih, bhh);
            k3_kernel<<<384, 256>>>(wihr, whh, bih, bhh);
        }
    }

    final_kernel<<<BB, 256>>>(fcfw, fcfb, out);
}

// round 12
// speedup vs baseline: 1.1522x; 1.1522x over previous
#include <cuda_runtime.h>
#include <cuda_bf16.h>
#include <math_constants.h>

// Problem constants
#define BB   512
#define T1   127
#define EE   256
#define HH   256
#define G4   1024
#define NL   3
#define BH   (BB*HH)

// ---------------- device scratch ----------------
__device__ __nv_bfloat16 g_encproj_bf[(size_t)BB * T1 * EE];  // 33.3 MB
__device__ float g_qproj[BB * EE];
__device__ float g_gates[(size_t)NL * BB * G4];    // Whh-part + biases
__device__ float g_h[NL * BH];
__device__ float g_c[NL * BH];
__device__ float g_context[BB * EE];

// ---------------- fast math helpers ----------------
__device__ __forceinline__ float tanha(float x) {
    float r; asm("tanh.approx.f32 %0, %1;" : "=f"(r) : "f"(x)); return r;
}
__device__ __forceinline__ float ex2f(float x) {
    float r; asm("ex2.approx.f32 %0, %1;" : "=f"(r) : "f"(x)); return r;
}
__device__ __forceinline__ float rcpf(float x) {
    float r; asm("rcp.approx.f32 %0, %1;" : "=f"(r) : "f"(x)); return r;
}
__device__ __forceinline__ float sigf(float x) {
    return rcpf(1.0f + ex2f(-1.4426950408889634f * x));
}
__device__ __forceinline__ float tanh_ex(float x) {
    float z = ex2f(2.8853900817779268f * x);
    return fmaf(-2.0f, rcpf(z + 1.0f), 1.0f);
}
__device__ __forceinline__ float2 ffma2(float2 a, float2 b, float2 c) {
    union U { float2 f; unsigned long long u; };
    U ua, ub, uc, ud;
    ua.f = a; ub.f = b; uc.f = c;
    asm("fma.rn.f32x2 %0, %1, %2, %3;" : "=l"(ud.u) : "l"(ua.u), "l"(ub.u), "l"(uc.u));
    return ud.f;
}
// streaming loads (evict-first): single-use sweeps must not evict weights from L2
__device__ __forceinline__ float ldcs_f(const float* p) {
    float v; asm volatile("ld.global.cs.f32 %0, [%1];" : "=f"(v) : "l"(p)); return v;
}
__device__ __forceinline__ unsigned ldcs_u32(const unsigned* p) {
    unsigned v; asm volatile("ld.global.cs.u32 %0, [%1];" : "=r"(v) : "l"(p)); return v;
}

// ---------------- 64x64 tile GEMM core (micro 4x4, f32x2) ----------------
__device__ __forceinline__ void mm64_inner(const float (*As)[68], const float (*Ws)[68],
                                           float2 acc[4][2], int tx, int ty)
{
#pragma unroll
    for (int kk = 0; kk < 32; kk++) {
        float4 a = *(const float4*)&As[kk][ty * 4];
        float4 w = *(const float4*)&Ws[kk][tx * 4];
        float2 wlo = make_float2(w.x, w.y), whi = make_float2(w.z, w.w);
        acc[0][0] = ffma2(make_float2(a.x, a.x), wlo, acc[0][0]);
        acc[0][1] = ffma2(make_float2(a.x, a.x), whi, acc[0][1]);
        acc[1][0] = ffma2(make_float2(a.y, a.y), wlo, acc[1][0]);
        acc[1][1] = ffma2(make_float2(a.y, a.y), whi, acc[1][1]);
        acc[2][0] = ffma2(make_float2(a.z, a.z), wlo, acc[2][0]);
        acc[2][1] = ffma2(make_float2(a.z, a.z), whi, acc[2][1]);
        acc[3][0] = ffma2(make_float2(a.w, a.w), wlo, acc[3][0]);
        acc[3][1] = ffma2(make_float2(a.w, a.w), whi, acc[3][1]);
    }
}

#define TILE_WR(dst, v0, v1, kq, r) \
    dst[(kq)+0][r]=v0.x; dst[(kq)+1][r]=v0.y; dst[(kq)+2][r]=v0.z; dst[(kq)+3][r]=v0.w; \
    dst[(kq)+4][r]=v1.x; dst[(kq)+5][r]=v1.y; dst[(kq)+6][r]=v1.z; dst[(kq)+7][r]=v1.w;

// ---------------- Whh-gates tile, NON-prefetched (used in k1 dual blocks) ----------------
__device__ void gates_tile_t(int l, int r, const float* __restrict__ whh,
                             const float* __restrict__ bih, const float* __restrict__ bhh,
                             float (*As)[68], float (*Ws)[68], int tid)
{
    const int tx = tid & 15, ty = tid >> 4;
    const int rl = tid & 63, kq = (tid >> 6) * 8;
    const int b0 = (r & 7) * 64, gu0 = (r >> 3) * 64;
    const float* S = g_h + l * BH;
    const float* W = whh + (size_t)l * G4 * HH;

    float2 acc[4][2];
#pragma unroll
    for (int i = 0; i < 4; i++) { acc[i][0] = make_float2(0.f, 0.f); acc[i][1] = make_float2(0.f, 0.f); }

    for (int kc = 0; kc < 256; kc += 32) {
        const float* sp = &S[(size_t)(b0 + rl) * 256 + kc + kq];
        float4 v0 = *(const float4*)sp, v1 = *(const float4*)(sp + 4);
        const float* wp = &W[(size_t)(gu0 + rl) * 256 + kc + kq];
        float4 u0 = *(const float4*)wp, u1 = *(const float4*)(wp + 4);
        TILE_WR(As, v0, v1, kq, rl);
        TILE_WR(Ws, u0, u1, kq, rl);
        __syncthreads();
        mm64_inner(As, Ws, acc, tx, ty);
        __syncthreads();
    }
    const int gu = gu0 + tx * 4;
    float4 bb1 = *(const float4*)&bih[l * G4 + gu];
    float4 bb2 = *(const float4*)&bhh[l * G4 + gu];
#pragma unroll
    for (int i = 0; i < 4; i++) {
        float4 o = make_float4(acc[i][0].x + bb1.x + bb2.x,
                               acc[i][0].y + bb1.y + bb2.y,
                               acc[i][1].x + bb1.z + bb2.z,
                               acc[i][1].y + bb1.w + bb2.w);
        *(float4*)&g_gates[((size_t)l * BB + b0 + ty * 4 + i) * G4 + gu] = o;
    }
}

// ---------------- Whh-gates tile, register-prefetched (R8-proven; k2/k3) ----------------
__device__ void gates_tile_pf(int l, int r, const float* __restrict__ whh,
                              const float* __restrict__ bih, const float* __restrict__ bhh,
                              float (*As)[68], float (*Ws)[68], int tid)
{
    const int tx = tid & 15, ty = tid >> 4;
    const int rl = tid & 63, kq = (tid >> 6) * 8;
    const int b0 = (r & 7) * 64, gu0 = (r >> 3) * 64;
    const float* S = g_h + l * BH;
    const float* W = whh + (size_t)l * G4 * HH;

    float2 acc[4][2];
#pragma unroll
    for (int i = 0; i < 4; i++) { acc[i][0] = make_float2(0.f, 0.f); acc[i][1] = make_float2(0.f, 0.f); }

    const float* sp0 = &S[(size_t)(b0 + rl) * 256 + kq];
    float4 pv0 = *(const float4*)sp0, pv1 = *(const float4*)(sp0 + 4);
    const float* wp0 = &W[(size_t)(gu0 + rl) * 256 + kq];
    float4 pw0 = *(const float4*)wp0, pw1 = *(const float4*)(wp0 + 4);
#pragma unroll 1
    for (int kci = 0; kci < 8; kci++) {
        __syncthreads();
        TILE_WR(As, pv0, pv1, kq, rl);
        TILE_WR(Ws, pw0, pw1, kq, rl);
        __syncthreads();
        if (kci + 1 < 8) {
            int kn = (kci + 1) * 32;
            const float* sp = &S[(size_t)(b0 + rl) * 256 + kn + kq];
            pv0 = *(const float4*)sp; pv1 = *(const float4*)(sp + 4);
            const float* wp = &W[(size_t)(gu0 + rl) * 256 + kn + kq];
            pw0 = *(const float4*)wp; pw1 = *(const float4*)(wp + 4);
        }
        mm64_inner(As, Ws, acc, tx, ty);
    }
    const int gu = gu0 + tx * 4;
    float4 bb1 = *(const float4*)&bih[l * G4 + gu];
    float4 bb2 = *(const float4*)&bhh[l * G4 + gu];
#pragma unroll
    for (int i = 0; i < 4; i++) {
        float4 o = make_float4(acc[i][0].x + bb1.x + bb2.x,
                               acc[i][0].y + bb1.y + bb2.y,
                               acc[i][1].x + bb1.z + bb2.z,
                               acc[i][1].y + bb1.w + bb2.w);
        *(float4*)&g_gates[((size_t)l * BB + b0 + ty * 4 + i) * G4 + gu] = o;
    }
}

// ---------------- qproj tile, register-prefetched (R8-proven) ----------------
__device__ void qproj_tile_pf(int qb, const float* __restrict__ w1,
                              float (*As)[68], float (*Ws)[68], int tid)
{
    const int tx = tid & 15, ty = tid >> 4;
    const int rl = tid & 63, kq = (tid >> 6) * 8;
    const int b0 = (qb & 7) * 64, f0 = (qb >> 3) * 64;

    float2 acc[4][2];
#pragma unroll
    for (int i = 0; i < 4; i++) { acc[i][0] = make_float2(0.f, 0.f); acc[i][1] = make_float2(0.f, 0.f); }

    const float* sp0 = &g_h[(b0 + rl) * 256 + kq];
    float4 pv0 = *(const float4*)sp0, pv1 = *(const float4*)(sp0 + 4);
    const float* wp0 = &w1[(size_t)(f0 + rl) * 768 + kq];
    float4 pw0 = *(const float4*)wp0, pw1 = *(const float4*)(wp0 + 4);
#pragma unroll 1
    for (int kci = 0; kci < 16; kci++) {
        __syncthreads();
        TILE_WR(As, pv0, pv1, kq, rl);
        TILE_WR(Ws, pw0, pw1, kq, rl);
        __syncthreads();
        if (kci + 1 < 16) {
            int kn = (kci + 1) * 32;
            const float* S = (kn < 256) ? g_h : g_c;      // [h0;c0]
            const float* sp = &S[(b0 + rl) * 256 + (kn & 255) + kq];
            pv0 = *(const float4*)sp; pv1 = *(const float4*)(sp + 4);
            const float* wp = &w1[(size_t)(f0 + rl) * 768 + kn + kq];
            pw0 = *(const float4*)wp; pw1 = *(const float4*)(wp + 4);
        }
        mm64_inner(As, Ws, acc, tx, ty);
    }
#pragma unroll
    for (int i = 0; i < 4; i++) {
        float4 o = make_float4(acc[i][0].x, acc[i][0].y, acc[i][1].x, acc[i][1].y);
        *(float4*)&g_qproj[(b0 + ty * 4 + i) * 256 + f0 + tx * 4] = o;
    }
}

// ---------------- LSTM layer tile, register-prefetched (R8-proven) ----------------
__device__ void lstm_tile_pf(int l, int fbid, const float* __restrict__ wihr,
                             float (*xs)[34], float (*ws)[32][34], int tid)
{
    const int b0 = (fbid & 15) * 32;
    const int u0 = (fbid >> 4) * 32;
    const int tx = tid & 15, ty = tid >> 4;
    const int ul = tx * 2, bl = ty * 2;

    const float* hin = g_h + (l - 1) * BH;
    const float* Wih = wihr + (size_t)(l - 1) * G4 * HH;

    float2 acc[2][4];
#pragma unroll
    for (int i = 0; i < 2; i++)
#pragma unroll
        for (int g = 0; g < 4; g++) acc[i][g] = make_float2(0.f, 0.f);

    const int ldb = tid >> 3, ldk = (tid & 7) * 4;
    const int wu = (tid >> 3) & 31, wkq = (tid & 7) * 4;

    float4 pst = *(const float4*)&hin[(size_t)(b0 + ldb) * 256 + ldk];
    float4 pw[4];
#pragma unroll
    for (int j = 0; j < 4; j++)
        pw[j] = *(const float4*)&Wih[(size_t)((j << 8) + u0 + wu) * 256 + wkq];

#pragma unroll 1
    for (int kci = 0; kci < 8; kci++) {
        __syncthreads();
        xs[ldk + 0][ldb] = pst.x; xs[ldk + 1][ldb] = pst.y;
        xs[ldk + 2][ldb] = pst.z; xs[ldk + 3][ldb] = pst.w;
#pragma unroll
        for (int j = 0; j < 4; j++) {
            ws[j][wkq + 0][wu] = pw[j].x; ws[j][wkq + 1][wu] = pw[j].y;
            ws[j][wkq + 2][wu] = pw[j].z; ws[j][wkq + 3][wu] = pw[j].w;
        }
        __syncthreads();
        if (kci + 1 < 8) {
            int kn = (kci + 1) * 32;
            pst = *(const float4*)&hin[(size_t)(b0 + ldb) * 256 + kn + ldk];
#pragma unroll
            for (int j = 0; j < 4; j++)
                pw[j] = *(const float4*)&Wih[(size_t)((j << 8) + u0 + wu) * 256 + kn + wkq];
        }
#pragma unroll
        for (int kk = 0; kk < 32; kk++) {
            float2 a = *(const float2*)&xs[kk][bl];
            float2 ax = make_float2(a.x, a.x);
            float2 ay = make_float2(a.y, a.y);
#pragma unroll
            for (int g = 0; g < 4; g++) {
                float2 w = *(const float2*)&ws[g][kk][ul];
                acc[0][g] = ffma2(ax, w, acc[0][g]);
                acc[1][g] = ffma2(ay, w, acc[1][g]);
            }
        }
    }

#pragma unroll
    for (int i = 0; i < 2; i++) {
#pragma unroll
        for (int j = 0; j < 2; j++) {
            int b = b0 + bl + i;
            int u = u0 + ul + j;
            const float* gb = &g_gates[((size_t)l * BB + b) * G4];
            float gi = (j ? acc[i][0].y : acc[i][0].x) + gb[0 * 256 + u];
            float gf = (j ? acc[i][1].y : acc[i][1].x) + gb[1 * 256 + u];
            float gg = (j ? acc[i][2].y : acc[i][2].x) + gb[2 * 256 + u];
            float go = (j ? acc[i][3].y : acc[i][3].x) + gb[3 * 256 + u];
            float co = g_c[l * BH + b * 256 + u];
            float cn = sigf(gf) * co + sigf(gi) * tanh_ex(gg);
            float hn = sigf(go) * tanh_ex(cn);
            g_c[l * BH + b * 256 + u] = cn;
            g_h[l * BH + b * 256 + u] = hn;
        }
    }
}

// ---------------- init: h=c=0, qproj=0, gates0/gates1 = biases ----------------
__global__ __launch_bounds__(256) void init_kernel(
    const float* __restrict__ bih, const float* __restrict__ bhh)
{
    int i = blockIdx.x * blockDim.x + threadIdx.x;
    if (i < NL * BH) { g_h[i] = 0.0f; g_c[i] = 0.0f; }
    if (i < BB * EE) g_qproj[i] = 0.0f;
    if (i < BB * G4) {
        int gu = i & 1023;
        g_gates[i] = bih[gu] + bhh[gu];                              // layer 0
        g_gates[(size_t)BB * G4 + i] = bih[G4 + gu] + bhh[G4 + gu];  // layer 1
    }
}

// ---------------- enc_proj GEMM (once), bf16 output ----------------
__global__ __launch_bounds__(256) void encproj_kernel(
    const float* __restrict__ x, const float* __restrict__ w1,
    const float* __restrict__ b1)
{
    __shared__ float As[32][68];
    __shared__ float Ws[32][68];
    const int m0 = blockIdx.x * 64;
    const int f0 = blockIdx.y * 64;
    const int tid = threadIdx.x;
    const int tx = tid & 15, ty = tid >> 4;
    const int rl = tid & 63, kq = (tid >> 6) * 8;

    float2 acc[4][2];
#pragma unroll
    for (int i = 0; i < 4; i++) { acc[i][0] = make_float2(0.f, 0.f); acc[i][1] = make_float2(0.f, 0.f); }

    for (int kc = 0; kc < 256; kc += 32) {
        const float* sp = &x[(size_t)(m0 + rl) * 256 + kc + kq];
        float4 v0 = *(const float4*)sp, v1 = *(const float4*)(sp + 4);
        const float* wp = &w1[(size_t)(f0 + rl) * 768 + 512 + kc + kq];
        float4 u0 = *(const float4*)wp, u1 = *(const float4*)(wp + 4);
        TILE_WR(As, v0, v1, kq, rl);
        TILE_WR(Ws, u0, u1, kq, rl);
        __syncthreads();
        mm64_inner(As, Ws, acc, tx, ty);
        __syncthreads();
    }

    float4 bias = *(const float4*)&b1[f0 + tx * 4];
#pragma unroll
    for (int i = 0; i < 4; i++) {
        __nv_bfloat162 p0, p1;
        p0.x = __float2bfloat16_rn(acc[i][0].x + bias.x);
        p0.y = __float2bfloat16_rn(acc[i][0].y + bias.y);
        p1.x = __float2bfloat16_rn(acc[i][1].x + bias.z);
        p1.y = __float2bfloat16_rn(acc[i][1].y + bias.w);
        __nv_bfloat162* dst = (__nv_bfloat162*)&g_encproj_bf[(size_t)(m0 + ty * 4 + i) * 256 + f0 + tx * 4];
        dst[0] = p0; dst[1] = p1;
    }
}

// ---------------- K1: fused attention (512thr/block) + gates2 dual-tile (R10) ----------------
__global__ __launch_bounds__(512) void k1_kernel(
    const float* __restrict__ x,    const float* __restrict__ yh,
    const float* __restrict__ w2,   const float* __restrict__ fcw,
    const float* __restrict__ fcb,  const float* __restrict__ wih0,
    const float* __restrict__ whh,  const float* __restrict__ bih,
    const float* __restrict__ bhh,  int s)
{
    __shared__ float s_g[2][64][68];            // two gate tiles (dual)
    __shared__ float s_qp[256], s_w2[256], s_sc[128];
    __shared__ float s_m[4], s_s[4];
    __shared__ float s_ctx[2][256];
    __shared__ float s_y[8];
    __shared__ float s_inv, s_yt;

    const int bid = blockIdx.x;
    const int tid = threadIdx.x;

    if (bid < 64) {                              // gates for layer 2, 2 tiles per block
        const int half = tid >> 8, st = tid & 255;
        gates_tile_t(2, bid * 2 + half, whh, bih, bhh,
                     (float(*)[68])&s_g[half][0], (float(*)[68])&s_g[half][32], st);
        return;
    }
    const int b = bid - 64;
    const int warp = tid >> 5, lane = tid & 31;

    if (tid < 256) { s_qp[tid] = g_qproj[b * 256 + tid]; s_w2[tid] = w2[tid]; }
    __syncthreads();

    // scores -> s_sc (16 warps, ~8 t each); enc_proj is single-use -> streaming load
    for (int t = warp; t < T1; t += 16) {
        const unsigned* er =
            (const unsigned*)(g_encproj_bf + ((size_t)b * T1 + t) * 256);
        float ps = 0.0f;
#pragma unroll
        for (int i = 0; i < 4; i++) {
            int e2 = lane + i * 32;
            unsigned raw = ldcs_u32(er + e2);
            __nv_bfloat162 evb = *(__nv_bfloat162*)&raw;
            float2 ev = __bfloat1622float2(evb);
            int e = e2 * 2;
            ps += s_w2[e]     * tanha(s_qp[e]     + ev.x);
            ps += s_w2[e + 1] * tanha(s_qp[e + 1] + ev.y);
        }
#pragma unroll
        for (int o = 16; o; o >>= 1) ps += __shfl_xor_sync(0xffffffffu, ps, o);
        if (lane == 0) s_sc[t] = ps;
    }
    __syncthreads();

    // softmax over 127 (threads 0..127, warps 0..3)
    if (tid < 128) {
        float v = (tid < T1) ? s_sc[tid] : -CUDART_INF_F;
        float m = v;
#pragma unroll
        for (int o = 16; o; o >>= 1) m = fmaxf(m, __shfl_xor_sync(0xffffffffu, m, o));
        if (lane == 0) s_m[warp] = m;
    }
    __syncthreads();
    if (tid < 128) {
        float mx = fmaxf(fmaxf(s_m[0], s_m[1]), fmaxf(s_m[2], s_m[3]));
        float v = (tid < T1) ? s_sc[tid] : -CUDART_INF_F;
        float e_ = (tid < T1) ? ex2f((v - mx) * 1.4426950408889634f) : 0.0f;
        float ss = e_;
#pragma unroll
        for (int o = 16; o; o >>= 1) ss += __shfl_xor_sync(0xffffffffu, ss, o);
        if (lane == 0) s_s[warp] = ss;
        s_sc[tid] = e_;
    }
    __syncthreads();
    if (tid == 0) s_inv = 1.0f / (s_s[0] + s_s[1] + s_s[2] + s_s[3]);
    __syncthreads();

    // context: x is single-use per step -> streaming loads (protects L2 weights)
    {
        const int e = tid & 255, half = tid >> 8;
        const int t0 = half * 64;
        const int t1 = (half == 0) ? 64 : T1;
        const float* xb = x + (size_t)b * T1 * 256 + e;
        float a0 = 0.f, a1 = 0.f, a2 = 0.f, a3 = 0.f;
        int t = t0;
#pragma unroll 2
        for (; t + 4 <= t1; t += 4) {
            a0 = fmaf(s_sc[t + 0], ldcs_f(&xb[(size_t)(t + 0) * 256]), a0);
            a1 = fmaf(s_sc[t + 1], ldcs_f(&xb[(size_t)(t + 1) * 256]), a1);
            a2 = fmaf(s_sc[t + 2], ldcs_f(&xb[(size_t)(t + 2) * 256]), a2);
            a3 = fmaf(s_sc[t + 3], ldcs_f(&xb[(size_t)(t + 3) * 256]), a3);
        }
        for (; t < t1; t++) a0 = fmaf(s_sc[t], ldcs_f(&xb[(size_t)t * 256]), a0);
        s_ctx[half][e] = (a0 + a1) + (a2 + a3);
    }
    __syncthreads();

    float ctx = 0.0f;
    if (tid < 256) {
        ctx = (s_ctx[0][tid] + s_ctx[1][tid]) * s_inv;
        g_context[b * 256 + tid] = ctx;
        float yv = ctx * fcw[tid];
#pragma unroll
        for (int o = 16; o; o >>= 1) yv += __shfl_xor_sync(0xffffffffu, yv, o);
        if (lane == 0) s_y[warp] = yv;
    }
    __syncthreads();
    if (tid == 0) {
        float tot = 0.0f;
#pragma unroll
        for (int w = 0; w < 8; w++) tot += s_y[w];
        s_yt = tot + yh[b * T1 + s] * fcw[256] + fcb[0];
    }
    __syncthreads();

    if (tid < 256) {
        const float yt = s_yt;
        const int u = tid;
        const float* gb = &g_gates[(size_t)b * G4];
        float gi = fmaf(yt, wih0[0 * 256 + u], gb[0 * 256 + u]);
        float gf = fmaf(yt, wih0[1 * 256 + u], gb[1 * 256 + u]);
        float gg = fmaf(yt, wih0[2 * 256 + u], gb[2 * 256 + u]);
        float go = fmaf(yt, wih0[3 * 256 + u], gb[3 * 256 + u]);
        float co = g_c[b * 256 + u];
        float cn = sigf(gf) * co + sigf(gi) * tanh_ex(gg);
        float hn = sigf(go) * tanh_ex(cn);
        g_c[b * 256 + u] = cn;
        g_h[b * 256 + u] = hn;
    }
}

// ---------------- K2: LSTM1(s) + qproj(s+1) + gates0(s+1), prefetched tiles ----------------
__global__ __launch_bounds__(256) void k2_kernel(
    const float* __restrict__ wihr, const float* __restrict__ w1,
    const float* __restrict__ whh,  const float* __restrict__ bih,
    const float* __restrict__ bhh)
{
    __shared__ float As[32][68];
    __shared__ float Ws[32][68];
    __shared__ float xs[32][34];
    __shared__ float ws[4][32][34];

    const int bid = blockIdx.x;
    if (bid < 32) {
        qproj_tile_pf(bid, w1, As, Ws, threadIdx.x);                    // qproj NEXT step
    } else if (bid < 160) {
        gates_tile_pf(0, bid - 32, whh, bih, bhh, As, Ws, threadIdx.x); // gates0 NEXT
    } else {
        lstm_tile_pf(1, bid - 160, wihr, xs, ws, threadIdx.x);          // LSTM layer 1 THIS step
    }
}

// ---------------- K3: LSTM2(s) + gates1(s+1), prefetched tiles ----------------
__global__ __launch_bounds__(256) void k3_kernel(
    const float* __restrict__ wihr, const float* __restrict__ whh,
    const float* __restrict__ bih,  const float* __restrict__ bhh)
{
    __shared__ float As[32][68];
    __shared__ float Ws[32][68];
    __shared__ float xs[32][34];
    __shared__ float ws[4][32][34];

    const int bid = blockIdx.x;
    if (bid < 128) {
        lstm_tile_pf(2, bid, wihr, xs, ws, threadIdx.x);                // LSTM layer 2 THIS step
    } else {
        gates_tile_pf(1, bid - 128, whh, bih, bhh, As, Ws, threadIdx.x); // gates1 NEXT
    }
}

// ---------------- final projection ----------------
__global__ __launch_bounds__(256) void final_kernel(
    const float* __restrict__ fcfw, const float* __restrict__ fcfb,
    float* __restrict__ out)
{
    const int b = blockIdx.x;
    const int tid = threadIdx.x;
    const int warp = tid >> 5, lane = tid & 31;
    __shared__ float s_r[8];

    float v = g_h[b * 256 + tid] * fcfw[tid]
            + g_context[b * 256 + tid] * fcfw[256 + tid];
#pragma unroll
    for (int o = 16; o; o >>= 1) v += __shfl_xor_sync(0xffffffffu, v, o);
    if (lane == 0) s_r[warp] = v;
    __syncthreads();
    if (tid == 0) {
        float tot = 0.0f;
#pragma unroll
        for (int w = 0; w < 8; w++) tot += s_r[w];
        out[b] = tot + fcfb[0];
    }
}

// ---------------- host launcher ----------------
extern "C" void kernel_launch(void* const* d_in, const int* in_sizes, int n_in,
                              void* d_out, int out_size)
{
    const float* x    = (const float*)d_in[0];
    const float* yh   = (const float*)d_in[1];
    const float* w1   = (const float*)d_in[2];
    const float* b1   = (const float*)d_in[3];
    const float* w2   = (const float*)d_in[4];
    const float* wih0 = (const float*)d_in[6];
    const float* wihr = (const float*)d_in[7];
    const float* whh  = (const float*)d_in[8];
    const float* bih  = (const float*)d_in[9];
    const float* bhh  = (const float*)d_in[10];
    const float* fcw  = (const float*)d_in[11];
    const float* fcb  = (const float*)d_in[12];
    const float* fcfw = (const float*)d_in[13];
    const float* fcfb = (const float*)d_in[14];
    float* out = (float*)d_out;

    init_kernel<<<2048, 256>>>(bih, bhh);
    encproj_kernel<<<dim3(1016, 4), 256>>>(x, w1, b1);

    for (int s = 0; s < T1; s++) {
        k1_kernel<<<576, 512>>>(x, yh, w2, fcw, fcb, wih0, whh, bih, bhh, s);
        if (s < T1 - 1) {
            k2_kernel<<<288, 256>>>(wihr, w1, whh, bih, bhh);
            k3_kernel<<<256, 256>>>(wihr, whh, bih, bhh);
        }
    }

    final_kernel<<<BB, 256>>>(fcfw, fcfb, out);
}

// round 13
// speedup vs baseline: 1.1729x; 1.0180x over previous
#include <cuda_runtime.h>
#include <cuda_bf16.h>
#include <math_constants.h>

// Problem constants
#define BB   512
#define T1   127
#define EE   256
#define HH   256
#define G4   1024
#define NL   3
#define BH   (BB*HH)

#define POOLF 5440   // floats per buffer: max(As+Ws = 2*2176, xs+ws = 1088+4352)

// ---------------- device scratch ----------------
__device__ __nv_bfloat16 g_encproj_bf[(size_t)BB * T1 * EE];  // 33.3 MB
__device__ float g_qproj[BB * EE];
__device__ float g_gates[(size_t)NL * BB * G4];    // Whh-part + biases
__device__ float g_h[NL * BH];
__device__ float g_c[NL * BH];
__device__ float g_context[BB * EE];

// ---------------- fast math helpers ----------------
__device__ __forceinline__ float tanha(float x) {
    float r; asm("tanh.approx.f32 %0, %1;" : "=f"(r) : "f"(x)); return r;
}
__device__ __forceinline__ float ex2f(float x) {
    float r; asm("ex2.approx.f32 %0, %1;" : "=f"(r) : "f"(x)); return r;
}
__device__ __forceinline__ float rcpf(float x) {
    float r; asm("rcp.approx.f32 %0, %1;" : "=f"(r) : "f"(x)); return r;
}
__device__ __forceinline__ float sigf(float x) {
    return rcpf(1.0f + ex2f(-1.4426950408889634f * x));
}
__device__ __forceinline__ float tanh_ex(float x) {
    float z = ex2f(2.8853900817779268f * x);
    return fmaf(-2.0f, rcpf(z + 1.0f), 1.0f);
}
__device__ __forceinline__ float2 ffma2(float2 a, float2 b, float2 c) {
    union U { float2 f; unsigned long long u; };
    U ua, ub, uc, ud;
    ua.f = a; ub.f = b; uc.f = c;
    asm("fma.rn.f32x2 %0, %1, %2, %3;" : "=l"(ud.u) : "l"(ua.u), "l"(ub.u), "l"(uc.u));
    return ud.f;
}
// streaming loads (evict-first): single-use sweeps must not evict weights from L2
__device__ __forceinline__ float ldcs_f(const float* p) {
    float v; asm volatile("ld.global.cs.f32 %0, [%1];" : "=f"(v) : "l"(p)); return v;
}
__device__ __forceinline__ unsigned ldcs_u32(const unsigned* p) {
    unsigned v; asm volatile("ld.global.cs.u32 %0, [%1];" : "=r"(v) : "l"(p)); return v;
}

// ---------------- 64x64 tile GEMM core (micro 4x4, f32x2) ----------------
__device__ __forceinline__ void mm64_inner(const float (*As)[68], const float (*Ws)[68],
                                           float2 acc[4][2], int tx, int ty)
{
#pragma unroll
    for (int kk = 0; kk < 32; kk++) {
        float4 a = *(const float4*)&As[kk][ty * 4];
        float4 w = *(const float4*)&Ws[kk][tx * 4];
        float2 wlo = make_float2(w.x, w.y), whi = make_float2(w.z, w.w);
        acc[0][0] = ffma2(make_float2(a.x, a.x), wlo, acc[0][0]);
        acc[0][1] = ffma2(make_float2(a.x, a.x), whi, acc[0][1]);
        acc[1][0] = ffma2(make_float2(a.y, a.y), wlo, acc[1][0]);
        acc[1][1] = ffma2(make_float2(a.y, a.y), whi, acc[1][1]);
        acc[2][0] = ffma2(make_float2(a.z, a.z), wlo, acc[2][0]);
        acc[2][1] = ffma2(make_float2(a.z, a.z), whi, acc[2][1]);
        acc[3][0] = ffma2(make_float2(a.w, a.w), wlo, acc[3][0]);
        acc[3][1] = ffma2(make_float2(a.w, a.w), whi, acc[3][1]);
    }
}

#define TILE_WR(dst, v0, v1, kq, r) \
    dst[(kq)+0][r]=v0.x; dst[(kq)+1][r]=v0.y; dst[(kq)+2][r]=v0.z; dst[(kq)+3][r]=v0.w; \
    dst[(kq)+4][r]=v1.x; dst[(kq)+5][r]=v1.y; dst[(kq)+6][r]=v1.z; dst[(kq)+7][r]=v1.w;

// ---------------- Whh-gates tile, NON-prefetched (used in k1 dual blocks) ----------------
__device__ void gates_tile_t(int l, int r, const float* __restrict__ whh,
                             const float* __restrict__ bih, const float* __restrict__ bhh,
                             float (*As)[68], float (*Ws)[68], int tid)
{
    const int tx = tid & 15, ty = tid >> 4;
    const int rl = tid & 63, kq = (tid >> 6) * 8;
    const int b0 = (r & 7) * 64, gu0 = (r >> 3) * 64;
    const float* S = g_h + l * BH;
    const float* W = whh + (size_t)l * G4 * HH;

    float2 acc[4][2];
#pragma unroll
    for (int i = 0; i < 4; i++) { acc[i][0] = make_float2(0.f, 0.f); acc[i][1] = make_float2(0.f, 0.f); }

    for (int kc = 0; kc < 256; kc += 32) {
        const float* sp = &S[(size_t)(b0 + rl) * 256 + kc + kq];
        float4 v0 = *(const float4*)sp, v1 = *(const float4*)(sp + 4);
        const float* wp = &W[(size_t)(gu0 + rl) * 256 + kc + kq];
        float4 u0 = *(const float4*)wp, u1 = *(const float4*)(wp + 4);
        TILE_WR(As, v0, v1, kq, rl);
        TILE_WR(Ws, u0, u1, kq, rl);
        __syncthreads();
        mm64_inner(As, Ws, acc, tx, ty);
        __syncthreads();
    }
    const int gu = gu0 + tx * 4;
    float4 bb1 = *(const float4*)&bih[l * G4 + gu];
    float4 bb2 = *(const float4*)&bhh[l * G4 + gu];
#pragma unroll
    for (int i = 0; i < 4; i++) {
        float4 o = make_float4(acc[i][0].x + bb1.x + bb2.x,
                               acc[i][0].y + bb1.y + bb2.y,
                               acc[i][1].x + bb1.z + bb2.z,
                               acc[i][1].y + bb1.w + bb2.w);
        *(float4*)&g_gates[((size_t)l * BB + b0 + ty * 4 + i) * G4 + gu] = o;
    }
}

// ---------------- Whh-gates tile, double-buffered + prefetched (k2/k3) ----------------
__device__ void gates_tile_db(int l, int r, const float* __restrict__ whh,
                              const float* __restrict__ bih, const float* __restrict__ bhh,
                              float (*pool)[POOLF], int tid)
{
    const int tx = tid & 15, ty = tid >> 4;
    const int rl = tid & 63, kq = (tid >> 6) * 8;
    const int b0 = (r & 7) * 64, gu0 = (r >> 3) * 64;
    const float* S = g_h + l * BH;
    const float* W = whh + (size_t)l * G4 * HH;

    float2 acc[4][2];
#pragma unroll
    for (int i = 0; i < 4; i++) { acc[i][0] = make_float2(0.f, 0.f); acc[i][1] = make_float2(0.f, 0.f); }

    // prefetch chunk 0 and store to buffer 0
    {
        const float* sp = &S[(size_t)(b0 + rl) * 256 + kq];
        float4 pv0 = *(const float4*)sp, pv1 = *(const float4*)(sp + 4);
        const float* wp = &W[(size_t)(gu0 + rl) * 256 + kq];
        float4 pw0 = *(const float4*)wp, pw1 = *(const float4*)(wp + 4);
        float (*As)[68] = (float(*)[68])&pool[0][0];
        float (*Ws)[68] = (float(*)[68])&pool[0][2176];
        TILE_WR(As, pv0, pv1, kq, rl);
        TILE_WR(Ws, pw0, pw1, kq, rl);
    }
    __syncthreads();

#pragma unroll 1
    for (int kci = 0; kci < 8; kci++) {
        float4 pv0, pv1, pw0, pw1;
        if (kci + 1 < 8) {
            int kn = (kci + 1) * 32;
            const float* sp = &S[(size_t)(b0 + rl) * 256 + kn + kq];
            pv0 = *(const float4*)sp; pv1 = *(const float4*)(sp + 4);
            const float* wp = &W[(size_t)(gu0 + rl) * 256 + kn + kq];
            pw0 = *(const float4*)wp; pw1 = *(const float4*)(wp + 4);
        }
        {
            float (*As)[68] = (float(*)[68])&pool[kci & 1][0];
            float (*Ws)[68] = (float(*)[68])&pool[kci & 1][2176];
            mm64_inner(As, Ws, acc, tx, ty);
        }
        if (kci + 1 < 8) {
            float (*An)[68] = (float(*)[68])&pool[(kci + 1) & 1][0];
            float (*Wn)[68] = (float(*)[68])&pool[(kci + 1) & 1][2176];
            TILE_WR(An, pv0, pv1, kq, rl);
            TILE_WR(Wn, pw0, pw1, kq, rl);
            __syncthreads();
        }
    }
    const int gu = gu0 + tx * 4;
    float4 bb1 = *(const float4*)&bih[l * G4 + gu];
    float4 bb2 = *(const float4*)&bhh[l * G4 + gu];
#pragma unroll
    for (int i = 0; i < 4; i++) {
        float4 o = make_float4(acc[i][0].x + bb1.x + bb2.x,
                               acc[i][0].y + bb1.y + bb2.y,
                               acc[i][1].x + bb1.z + bb2.z,
                               acc[i][1].y + bb1.w + bb2.w);
        *(float4*)&g_gates[((size_t)l * BB + b0 + ty * 4 + i) * G4 + gu] = o;
    }
    __syncthreads();   // block may host another tile next launch; keep smem safe
}

// ---------------- qproj tile, double-buffered + prefetched ----------------
__device__ void qproj_tile_db(int qb, const float* __restrict__ w1,
                              float (*pool)[POOLF], int tid)
{
    const int tx = tid & 15, ty = tid >> 4;
    const int rl = tid & 63, kq = (tid >> 6) * 8;
    const int b0 = (qb & 7) * 64, f0 = (qb >> 3) * 64;

    float2 acc[4][2];
#pragma unroll
    for (int i = 0; i < 4; i++) { acc[i][0] = make_float2(0.f, 0.f); acc[i][1] = make_float2(0.f, 0.f); }

    {
        const float* sp = &g_h[(b0 + rl) * 256 + kq];
        float4 pv0 = *(const float4*)sp, pv1 = *(const float4*)(sp + 4);
        const float* wp = &w1[(size_t)(f0 + rl) * 768 + kq];
        float4 pw0 = *(const float4*)wp, pw1 = *(const float4*)(wp + 4);
        float (*As)[68] = (float(*)[68])&pool[0][0];
        float (*Ws)[68] = (float(*)[68])&pool[0][2176];
        TILE_WR(As, pv0, pv1, kq, rl);
        TILE_WR(Ws, pw0, pw1, kq, rl);
    }
    __syncthreads();

#pragma unroll 1
    for (int kci = 0; kci < 16; kci++) {
        float4 pv0, pv1, pw0, pw1;
        if (kci + 1 < 16) {
            int kn = (kci + 1) * 32;
            const float* S = (kn < 256) ? g_h : g_c;      // [h0;c0]
            const float* sp = &S[(b0 + rl) * 256 + (kn & 255) + kq];
            pv0 = *(const float4*)sp; pv1 = *(const float4*)(sp + 4);
            const float* wp = &w1[(size_t)(f0 + rl) * 768 + kn + kq];
            pw0 = *(const float4*)wp; pw1 = *(const float4*)(wp + 4);
        }
        {
            float (*As)[68] = (float(*)[68])&pool[kci & 1][0];
            float (*Ws)[68] = (float(*)[68])&pool[kci & 1][2176];
            mm64_inner(As, Ws, acc, tx, ty);
        }
        if (kci + 1 < 16) {
            float (*An)[68] = (float(*)[68])&pool[(kci + 1) & 1][0];
            float (*Wn)[68] = (float(*)[68])&pool[(kci + 1) & 1][2176];
            TILE_WR(An, pv0, pv1, kq, rl);
            TILE_WR(Wn, pw0, pw1, kq, rl);
            __syncthreads();
        }
    }
#pragma unroll
    for (int i = 0; i < 4; i++) {
        float4 o = make_float4(acc[i][0].x, acc[i][0].y, acc[i][1].x, acc[i][1].y);
        *(float4*)&g_qproj[(b0 + ty * 4 + i) * 256 + f0 + tx * 4] = o;
    }
    __syncthreads();
}

// ---------------- LSTM layer tile, double-buffered + prefetched ----------------
__device__ void lstm_tile_db(int l, int fbid, const float* __restrict__ wihr,
                             float (*pool)[POOLF], int tid)
{
    const int b0 = (fbid & 15) * 32;
    const int u0 = (fbid >> 4) * 32;
    const int tx = tid & 15, ty = tid >> 4;
    const int ul = tx * 2, bl = ty * 2;

    const float* hin = g_h + (l - 1) * BH;
    const float* Wih = wihr + (size_t)(l - 1) * G4 * HH;

    float2 acc[2][4];
#pragma unroll
    for (int i = 0; i < 2; i++)
#pragma unroll
        for (int g = 0; g < 4; g++) acc[i][g] = make_float2(0.f, 0.f);

    const int ldb = tid >> 3, ldk = (tid & 7) * 4;
    const int wu = (tid >> 3) & 31, wkq = (tid & 7) * 4;

    // xs at pool[buf][0..1088), ws at pool[buf][1088..5440)
    {
        float4 pst = *(const float4*)&hin[(size_t)(b0 + ldb) * 256 + ldk];
        float4 pw[4];
#pragma unroll
        for (int j = 0; j < 4; j++)
            pw[j] = *(const float4*)&Wih[(size_t)((j << 8) + u0 + wu) * 256 + wkq];
        float (*xs)[34] = (float(*)[34])&pool[0][0];
        float (*ws)[32][34] = (float(*)[32][34])&pool[0][1088];
        xs[ldk + 0][ldb] = pst.x; xs[ldk + 1][ldb] = pst.y;
        xs[ldk + 2][ldb] = pst.z; xs[ldk + 3][ldb] = pst.w;
#pragma unroll
        for (int j = 0; j < 4; j++) {
            ws[j][wkq + 0][wu] = pw[j].x; ws[j][wkq + 1][wu] = pw[j].y;
            ws[j][wkq + 2][wu] = pw[j].z; ws[j][wkq + 3][wu] = pw[j].w;
        }
    }
    __syncthreads();

#pragma unroll 1
    for (int kci = 0; kci < 8; kci++) {
        float4 pst, pw[4];
        if (kci + 1 < 8) {
            int kn = (kci + 1) * 32;
            pst = *(const float4*)&hin[(size_t)(b0 + ldb) * 256 + kn + ldk];
#pragma unroll
            for (int j = 0; j < 4; j++)
                pw[j] = *(const float4*)&Wih[(size_t)((j << 8) + u0 + wu) * 256 + kn + wkq];
        }
        {
            float (*xs)[34] = (float(*)[34])&pool[kci & 1][0];
            float (*ws)[32][34] = (float(*)[32][34])&pool[kci & 1][1088];
#pragma unroll
            for (int kk = 0; kk < 32; kk++) {
                float2 a = *(const float2*)&xs[kk][bl];
                float2 ax = make_float2(a.x, a.x);
                float2 ay = make_float2(a.y, a.y);
#pragma unroll
                for (int g = 0; g < 4; g++) {
                    float2 w = *(const float2*)&ws[g][kk][ul];
                    acc[0][g] = ffma2(ax, w, acc[0][g]);
                    acc[1][g] = ffma2(ay, w, acc[1][g]);
                }
            }
        }
        if (kci + 1 < 8) {
            float (*xn)[34] = (float(*)[34])&pool[(kci + 1) & 1][0];
            float (*wn)[32][34] = (float(*)[32][34])&pool[(kci + 1) & 1][1088];
            xn[ldk + 0][ldb] = pst.x; xn[ldk + 1][ldb] = pst.y;
            xn[ldk + 2][ldb] = pst.z; xn[ldk + 3][ldb] = pst.w;
#pragma unroll
            for (int j = 0; j < 4; j++) {
                wn[j][wkq + 0][wu] = pw[j].x; wn[j][wkq + 1][wu] = pw[j].y;
                wn[j][wkq + 2][wu] = pw[j].z; wn[j][wkq + 3][wu] = pw[j].w;
            }
            __syncthreads();
        }
    }

#pragma unroll
    for (int i = 0; i < 2; i++) {
#pragma unroll
        for (int j = 0; j < 2; j++) {
            int b = b0 + bl + i;
            int u = u0 + ul + j;
            const float* gb = &g_gates[((size_t)l * BB + b) * G4];
            float gi = (j ? acc[i][0].y : acc[i][0].x) + gb[0 * 256 + u];
            float gf = (j ? acc[i][1].y : acc[i][1].x) + gb[1 * 256 + u];
            float gg = (j ? acc[i][2].y : acc[i][2].x) + gb[2 * 256 + u];
            float go = (j ? acc[i][3].y : acc[i][3].x) + gb[3 * 256 + u];
            float co = g_c[l * BH + b * 256 + u];
            float cn = sigf(gf) * co + sigf(gi) * tanh_ex(gg);
            float hn = sigf(go) * tanh_ex(cn);
            g_c[l * BH + b * 256 + u] = cn;
            g_h[l * BH + b * 256 + u] = hn;
        }
    }
    __syncthreads();
}

// ---------------- init: h=c=0, qproj=0, gates0/gates1 = biases ----------------
__global__ __launch_bounds__(256) void init_kernel(
    const float* __restrict__ bih, const float* __restrict__ bhh)
{
    int i = blockIdx.x * blockDim.x + threadIdx.x;
    if (i < NL * BH) { g_h[i] = 0.0f; g_c[i] = 0.0f; }
    if (i < BB * EE) g_qproj[i] = 0.0f;
    if (i < BB * G4) {
        int gu = i & 1023;
        g_gates[i] = bih[gu] + bhh[gu];                              // layer 0
        g_gates[(size_t)BB * G4 + i] = bih[G4 + gu] + bhh[G4 + gu];  // layer 1
    }
}

// ---------------- enc_proj GEMM (once), bf16 output ----------------
__global__ __launch_bounds__(256) void encproj_kernel(
    const float* __restrict__ x, const float* __restrict__ w1,
    const float* __restrict__ b1)
{
    __shared__ float As[32][68];
    __shared__ float Ws[32][68];
    const int m0 = blockIdx.x * 64;
    const int f0 = blockIdx.y * 64;
    const int tid = threadIdx.x;
    const int tx = tid & 15, ty = tid >> 4;
    const int rl = tid & 63, kq = (tid >> 6) * 8;

    float2 acc[4][2];
#pragma unroll
    for (int i = 0; i < 4; i++) { acc[i][0] = make_float2(0.f, 0.f); acc[i][1] = make_float2(0.f, 0.f); }

    for (int kc = 0; kc < 256; kc += 32) {
        const float* sp = &x[(size_t)(m0 + rl) * 256 + kc + kq];
        float4 v0 = *(const float4*)sp, v1 = *(const float4*)(sp + 4);
        const float* wp = &w1[(size_t)(f0 + rl) * 768 + 512 + kc + kq];
        float4 u0 = *(const float4*)wp, u1 = *(const float4*)(wp + 4);
        TILE_WR(As, v0, v1, kq, rl);
        TILE_WR(Ws, u0, u1, kq, rl);
        __syncthreads();
        mm64_inner(As, Ws, acc, tx, ty);
        __syncthreads();
    }

    float4 bias = *(const float4*)&b1[f0 + tx * 4];
#pragma unroll
    for (int i = 0; i < 4; i++) {
        __nv_bfloat162 p0, p1;
        p0.x = __float2bfloat16_rn(acc[i][0].x + bias.x);
        p0.y = __float2bfloat16_rn(acc[i][0].y + bias.y);
        p1.x = __float2bfloat16_rn(acc[i][1].x + bias.z);
        p1.y = __float2bfloat16_rn(acc[i][1].y + bias.w);
        __nv_bfloat162* dst = (__nv_bfloat162*)&g_encproj_bf[(size_t)(m0 + ty * 4 + i) * 256 + f0 + tx * 4];
        dst[0] = p0; dst[1] = p1;
    }
}

// ---------------- K1: fused attention (512thr/block) + gates2 dual-tile (R12) ----------------
__global__ __launch_bounds__(512) void k1_kernel(
    const float* __restrict__ x,    const float* __restrict__ yh,
    const float* __restrict__ w2,   const float* __restrict__ fcw,
    const float* __restrict__ fcb,  const float* __restrict__ wih0,
    const float* __restrict__ whh,  const float* __restrict__ bih,
    const float* __restrict__ bhh,  int s)
{
    __shared__ float s_g[2][64][68];            // two gate tiles (dual)
    __shared__ float s_qp[256], s_w2[256], s_sc[128];
    __shared__ float s_m[4], s_s[4];
    __shared__ float s_ctx[2][256];
    __shared__ float s_y[8];
    __shared__ float s_inv, s_yt;

    const int bid = blockIdx.x;
    const int tid = threadIdx.x;

    if (bid < 64) {                              // gates for layer 2, 2 tiles per block
        const int half = tid >> 8, st = tid & 255;
        gates_tile_t(2, bid * 2 + half, whh, bih, bhh,
                     (float(*)[68])&s_g[half][0], (float(*)[68])&s_g[half][32], st);
        return;
    }
    const int b = bid - 64;
    const int warp = tid >> 5, lane = tid & 31;

    if (tid < 256) { s_qp[tid] = g_qproj[b * 256 + tid]; s_w2[tid] = w2[tid]; }
    __syncthreads();

    // scores -> s_sc; enc_proj is single-use -> streaming load
    for (int t = warp; t < T1; t += 16) {
        const unsigned* er =
            (const unsigned*)(g_encproj_bf + ((size_t)b * T1 + t) * 256);
        float ps = 0.0f;
#pragma unroll
        for (int i = 0; i < 4; i++) {
            int e2 = lane + i * 32;
            unsigned raw = ldcs_u32(er + e2);
            __nv_bfloat162 evb = *(__nv_bfloat162*)&raw;
            float2 ev = __bfloat1622float2(evb);
            int e = e2 * 2;
            ps += s_w2[e]     * tanha(s_qp[e]     + ev.x);
            ps += s_w2[e + 1] * tanha(s_qp[e + 1] + ev.y);
        }
#pragma unroll
        for (int o = 16; o; o >>= 1) ps += __shfl_xor_sync(0xffffffffu, ps, o);
        if (lane == 0) s_sc[t] = ps;
    }
    __syncthreads();

    if (tid < 128) {
        float v = (tid < T1) ? s_sc[tid] : -CUDART_INF_F;
        float m = v;
#pragma unroll
        for (int o = 16; o; o >>= 1) m = fmaxf(m, __shfl_xor_sync(0xffffffffu, m, o));
        if (lane == 0) s_m[warp] = m;
    }
    __syncthreads();
    if (tid < 128) {
        float mx = fmaxf(fmaxf(s_m[0], s_m[1]), fmaxf(s_m[2], s_m[3]));
        float v = (tid < T1) ? s_sc[tid] : -CUDART_INF_F;
        float e_ = (tid < T1) ? ex2f((v - mx) * 1.4426950408889634f) : 0.0f;
        float ss = e_;
#pragma unroll
        for (int o = 16; o; o >>= 1) ss += __shfl_xor_sync(0xffffffffu, ss, o);
        if (lane == 0) s_s[warp] = ss;
        s_sc[tid] = e_;
    }
    __syncthreads();
    if (tid == 0) s_inv = 1.0f / (s_s[0] + s_s[1] + s_s[2] + s_s[3]);
    __syncthreads();

    // context: x is single-use per step -> streaming loads (protects L2 weights)
    {
        const int e = tid & 255, half = tid >> 8;
        const int t0 = half * 64;
        const int t1 = (half == 0) ? 64 : T1;
        const float* xb = x + (size_t)b * T1 * 256 + e;
        float a0 = 0.f, a1 = 0.f, a2 = 0.f, a3 = 0.f;
        int t = t0;
#pragma unroll 2
        for (; t + 4 <= t1; t += 4) {
            a0 = fmaf(s_sc[t + 0], ldcs_f(&xb[(size_t)(t + 0) * 256]), a0);
            a1 = fmaf(s_sc[t + 1], ldcs_f(&xb[(size_t)(t + 1) * 256]), a1);
            a2 = fmaf(s_sc[t + 2], ldcs_f(&xb[(size_t)(t + 2) * 256]), a2);
            a3 = fmaf(s_sc[t + 3], ldcs_f(&xb[(size_t)(t + 3) * 256]), a3);
        }
        for (; t < t1; t++) a0 = fmaf(s_sc[t], ldcs_f(&xb[(size_t)t * 256]), a0);
        s_ctx[half][e] = (a0 + a1) + (a2 + a3);
    }
    __syncthreads();

    float ctx = 0.0f;
    if (tid < 256) {
        ctx = (s_ctx[0][tid] + s_ctx[1][tid]) * s_inv;
        g_context[b * 256 + tid] = ctx;
        float yv = ctx * fcw[tid];
#pragma unroll
        for (int o = 16; o; o >>= 1) yv += __shfl_xor_sync(0xffffffffu, yv, o);
        if (lane == 0) s_y[warp] = yv;
    }
    __syncthreads();
    if (tid == 0) {
        float tot = 0.0f;
#pragma unroll
        for (int w = 0; w < 8; w++) tot += s_y[w];
        s_yt = tot + yh[b * T1 + s] * fcw[256] + fcb[0];
    }
    __syncthreads();

    if (tid < 256) {
        const float yt = s_yt;
        const int u = tid;
        const float* gb = &g_gates[(size_t)b * G4];
        float gi = fmaf(yt, wih0[0 * 256 + u], gb[0 * 256 + u]);
        float gf = fmaf(yt, wih0[1 * 256 + u], gb[1 * 256 + u]);
        float gg = fmaf(yt, wih0[2 * 256 + u], gb[2 * 256 + u]);
        float go = fmaf(yt, wih0[3 * 256 + u], gb[3 * 256 + u]);
        float co = g_c[b * 256 + u];
        float cn = sigf(gf) * co + sigf(gi) * tanh_ex(gg);
        float hn = sigf(go) * tanh_ex(cn);
        g_c[b * 256 + u] = cn;
        g_h[b * 256 + u] = hn;
    }
}

// ---------------- K2: LSTM1(s) + qproj(s+1) + gates0(s+1), double-buffered ----------------
__global__ __launch_bounds__(256) void k2_kernel(
    const float* __restrict__ wihr, const float* __restrict__ w1,
    const float* __restrict__ whh,  const float* __restrict__ bih,
    const float* __restrict__ bhh)
{
    __shared__ float pool[2][POOLF];
    const int bid = blockIdx.x;
    if (bid < 32) {
        qproj_tile_db(bid, w1, pool, threadIdx.x);                     // qproj NEXT step
    } else if (bid < 160) {
        gates_tile_db(0, bid - 32, whh, bih, bhh, pool, threadIdx.x);  // gates0 NEXT
    } else {
        lstm_tile_db(1, bid - 160, wihr, pool, threadIdx.x);           // LSTM layer 1 THIS step
    }
}

// ---------------- K3: LSTM2(s) + gates1(s+1), double-buffered ----------------
__global__ __launch_bounds__(256) void k3_kernel(
    const float* __restrict__ wihr, const float* __restrict__ whh,
    const float* __restrict__ bih,  const float* __restrict__ bhh)
{
    __shared__ float pool[2][POOLF];
    const int bid = blockIdx.x;
    if (bid < 128) {
        lstm_tile_db(2, bid, wihr, pool, threadIdx.x);                 // LSTM layer 2 THIS step
    } else {
        gates_tile_db(1, bid - 128, whh, bih, bhh, pool, threadIdx.x); // gates1 NEXT
    }
}

// ---------------- final projection ----------------
__global__ __launch_bounds__(256) void final_kernel(
    const float* __restrict__ fcfw, const float* __restrict__ fcfb,
    float* __restrict__ out)
{
    const int b = blockIdx.x;
    const int tid = threadIdx.x;
    const int warp = tid >> 5, lane = tid & 31;
    __shared__ float s_r[8];

    float v = g_h[b * 256 + tid] * fcfw[tid]
            + g_context[b * 256 + tid] * fcfw[256 + tid];
#pragma unroll
    for (int o = 16; o; o >>= 1) v += __shfl_xor_sync(0xffffffffu, v, o);
    if (lane == 0) s_r[warp] = v;
    __syncthreads();
    if (tid == 0) {
        float tot = 0.0f;
#pragma unroll
        for (int w = 0; w < 8; w++) tot += s_r[w];
        out[b] = tot + fcfb[0];
    }
}

// ---------------- host launcher ----------------
extern "C" void kernel_launch(void* const* d_in, const int* in_sizes, int n_in,
                              void* d_out, int out_size)
{
    const float* x    = (const float*)d_in[0];
    const float* yh   = (const float*)d_in[1];
    const float* w1   = (const float*)d_in[2];
    const float* b1   = (const float*)d_in[3];
    const float* w2   = (const float*)d_in[4];
    const float* wih0 = (const float*)d_in[6];
    const float* wihr = (const float*)d_in[7];
    const float* whh  = (const float*)d_in[8];
    const float* bih  = (const float*)d_in[9];
    const float* bhh  = (const float*)d_in[10];
    const float* fcw  = (const float*)d_in[11];
    const float* fcb  = (const float*)d_in[12];
    const float* fcfw = (const float*)d_in[13];
    const float* fcfb = (const float*)d_in[14];
    float* out = (float*)d_out;

    init_kernel<<<2048, 256>>>(bih, bhh);
    encproj_kernel<<<dim3(1016, 4), 256>>>(x, w1, b1);

    for (int s = 0; s < T1; s++) {
        k1_kernel<<<576, 512>>>(x, yh, w2, fcw, fcb, wih0, whh, bih, bhh, s);
        if (s < T1 - 1) {
            k2_kernel<<<288, 256>>>(wihr, w1, whh, bih, bhh);
            k3_kernel<<<256, 256>>>(wihr, whh, bih, bhh);
        }
    }

    final_kernel<<<BB, 256>>>(fcfw, fcfb, out);
}